// round 8
// baseline (speedup 1.0000x reference)
#include <cuda_runtime.h>
#include <cuda_bf16.h>
#include <math.h>

#define BSZ  256
#define NN   1024
#define TT   100
#define NBLK 128
#define NTHR 256
#define TM   32
#define TN   64
#define KC   32
#define KHALF 512
#define NCHG  16            // chunks per warp-group
#define STAGE 12288         // A 4K (h|l interleaved) | Bh 4K | Bl 4K
#define GBYTES (2 * STAGE)  // per-group smem
#define SMEM_TOTAL (2 * GBYTES)   // 49152 = default dynamic limit

// Output layout (floats)
#define O_ACT 0
#define O_E3H 512
#define O_E5H (512 + 102400)
#define O_C1H (512 + 2*102400)
#define O_E3F (512 + 3*102400)
#define O_E5F (O_E3F + 262144)
#define O_C1F (O_E5F + 262144)

// ---- persistent device state ----
__device__ float g_ec5[BSZ*NN];
__device__ float g_ec3[BSZ*NN];
__device__ float g_ca1[BSZ*NN];
__device__ float g_drive[TT*NN];
__device__ __align__(16) __nv_bfloat16 g_ec3h[BSZ*NN], g_ec3l[BSZ*NN];
__device__ __align__(16) __nv_bfloat16 g_ca1h[BSZ*NN], g_ca1l[BSZ*NN];
__device__ __align__(16) __nv_bfloat16 g_ca3h[128*NN], g_ca3l[128*NN];
__device__ __align__(16) __nv_bfloat16 g_w0h[NN*NN], g_w0l[NN*NN];  // wca3ca1 [k][n]
__device__ __align__(16) __nv_bfloat16 g_w1h[NN*NN], g_w1l[NN*NN];  // wec3ca1 [k][n]
__device__ __align__(16) __nv_bfloat16 g_w2h[NN*NN], g_w2l[NN*NN];  // wca1ec5 [k][n]
__device__ unsigned g_full = 0;
__device__ unsigned g_grp[8 * 32];

__device__ __forceinline__ float sigm(float x) {
    return __fdividef(1.0f, 1.0f + __expf(-x));
}
__device__ __forceinline__ unsigned smem_u32(const void* p) {
    unsigned a;
    asm("{ .reg .u64 t; cvta.to.shared.u64 t, %1; cvt.u32.u64 %0, t; }" : "=r"(a) : "l"(p));
    return a;
}
#define SWZ128(o) ((unsigned)(o) ^ ((((unsigned)(o)) >> 3) & 0x70u))
#define GBAR(gid) asm volatile("bar.sync %0, 128;" :: "r"((gid) + 1) : "memory")

__device__ __forceinline__ void ldm_a(unsigned (&r)[4], unsigned a) {
    asm volatile("ldmatrix.sync.aligned.m8n8.x4.shared.b16 {%0,%1,%2,%3}, [%4];"
        : "=r"(r[0]), "=r"(r[1]), "=r"(r[2]), "=r"(r[3]) : "r"(a));
}
__device__ __forceinline__ void ldm_bt(unsigned (&r)[4], unsigned a) {
    asm volatile("ldmatrix.sync.aligned.m8n8.x4.trans.shared.b16 {%0,%1,%2,%3}, [%4];"
        : "=r"(r[0]), "=r"(r[1]), "=r"(r[2]), "=r"(r[3]) : "r"(a));
}
__device__ __forceinline__ void mma16816(float (&d)[4], const unsigned (&a)[4],
                                         unsigned b0, unsigned b1) {
    asm volatile(
        "mma.sync.aligned.m16n8k16.row.col.f32.bf16.bf16.f32 "
        "{%0,%1,%2,%3}, {%4,%5,%6,%7}, {%8,%9}, {%0,%1,%2,%3};"
        : "+f"(d[0]), "+f"(d[1]), "+f"(d[2]), "+f"(d[3])
        : "r"(a[0]), "r"(a[1]), "r"(a[2]), "r"(a[3]), "r"(b0), "r"(b1));
}

// Ticket barrier (race-free, wrap-safe; N power of 2)
__device__ __forceinline__ void ticket_sync(unsigned* ctr, unsigned N) {
    __syncthreads();
    if (threadIdx.x == 0) {
        __threadfence();
        const unsigned r    = atomicAdd(ctr, 1u);
        const unsigned goal = (r & ~(N - 1u)) + N;
        while ((*(volatile unsigned*)ctr) - r < goal - r) { }
        __threadfence();
    }
    __syncthreads();
}
#define FULL_SYNC()    ticket_sync(&g_full, NBLK)
#define GROUP_SYNC(g)  ticket_sync(&g_grp[(g) << 5], 16u)

// Split-K bf16-split HMMA GEMM: 32x64 tile over K=1024, two independent
// 4-warp pipelines (warp-group = tid>>7, K-half each, own smem + named bar).
// Warp p=(tid&127)>>5: wm=p>>1 (m16), wn=p&1 (n32). d[nb][.] = n8 block nb.
__device__ __forceinline__ void gemm_split(
    const __nv_bfloat16* __restrict__ Ah, const __nv_bfloat16* __restrict__ Al,
    const __nv_bfloat16* __restrict__ Bh, const __nv_bfloat16* __restrict__ Bl,
    int n0, char* sm, unsigned smb, float (&d)[4][4])
{
    const int tid = threadIdx.x;
    const int g   = tid >> 7, p = tid & 127;
    const int warp = p >> 5, lane = p & 31;
    const int wm = warp >> 1, wn = warp & 1;
    const int sel = lane >> 3, r8 = lane & 7;

#pragma unroll
    for (int i = 0; i < 4; i++)
#pragma unroll
        for (int j = 0; j < 4; j++) d[i][j] = 0.f;

    // loaders: A 32 rows x 4 quads (h and l, 1 each/thread); B 32 rows x 8
    // quads (2 each/thread per h/l)
    const int ar = p >> 2, aq = p & 3;
    const int br = p >> 3, bq = p & 7;
    const unsigned asoh = SWZ128(ar * 128 + aq * 16);
    const unsigned asol = SWZ128(ar * 128 + 64 + aq * 16);
    const unsigned bso0 = SWZ128(br * 128 + bq * 16);
    const unsigned bso1 = SWZ128((br + 16) * 128 + bq * 16);

    const int k0 = g * KHALF;
    const __nv_bfloat16* Agh  = Ah + ar * NN + k0 + aq * 8;
    const __nv_bfloat16* Agl  = Al + ar * NN + k0 + aq * 8;
    const __nv_bfloat16* Bgh0 = Bh + (k0 + br) * NN + n0 + bq * 8;
    const __nv_bfloat16* Bgh1 = Bh + (k0 + br + 16) * NN + n0 + bq * 8;
    const __nv_bfloat16* Bgl0 = Bl + (k0 + br) * NN + n0 + bq * 8;
    const __nv_bfloat16* Bgl1 = Bl + (k0 + br + 16) * NN + n0 + bq * 8;

    // ldmatrix tile-local offsets (pre-swizzle)
    const unsigned a_off = (unsigned)((wm * 16 + ((sel & 1) << 3) + r8) * 128
                                      + ((sel >> 1) << 4));
    const unsigned b_row = (unsigned)((((sel & 1) << 3) + r8) * 128);
    const unsigned b_col = (unsigned)((wn << 6) + ((sel >> 1) << 4));

    char* smg = sm + g * GBYTES;
    const unsigned abg = smb + g * GBYTES;

    uint4 pa, pal, pb0, pb1, pl0, pl1;
    pa  = *(const uint4*)(Agh);
    pal = *(const uint4*)(Agl);
    pb0 = *(const uint4*)(Bgh0);
    pb1 = *(const uint4*)(Bgh1);
    pl0 = *(const uint4*)(Bgl0);
    pl1 = *(const uint4*)(Bgl1);

    for (int c = 0; c < NCHG; c++) {
        char* sp = smg + (c & 1) * STAGE;
        *(uint4*)(sp + asoh)        = pa;
        *(uint4*)(sp + asol)        = pal;
        *(uint4*)(sp + 4096 + bso0) = pb0;
        *(uint4*)(sp + 4096 + bso1) = pb1;
        *(uint4*)(sp + 8192 + bso0) = pl0;
        *(uint4*)(sp + 8192 + bso1) = pl1;
        GBAR(g);

        if (c + 1 < NCHG) {
            const int ke = (c + 1) * KC;
            pa  = *(const uint4*)(Agh + ke);
            pal = *(const uint4*)(Agl + ke);
            pb0 = *(const uint4*)(Bgh0 + ke * NN);
            pb1 = *(const uint4*)(Bgh1 + ke * NN);
            pl0 = *(const uint4*)(Bgl0 + ke * NN);
            pl1 = *(const uint4*)(Bgl1 + ke * NN);
        }

        const unsigned ab = abg + (c & 1) * STAGE;
#pragma unroll
        for (int ks = 0; ks < 2; ks++) {
            unsigned ah[4], al4[4];
            ldm_a(ah,  ab + SWZ128(a_off + ks * 32));
            ldm_a(al4, ab + SWZ128(a_off + ks * 32 + 64));
#pragma unroll
            for (int nh = 0; nh < 2; nh++) {
                unsigned bh[4], bl[4];
                const unsigned bo = ab + 4096
                    + SWZ128(b_row + ks * 2048 + b_col + nh * 32);
                ldm_bt(bh, bo);
                ldm_bt(bl, bo + 4096);
                mma16816(d[2*nh],   ah,  bh[0], bh[1]);
                mma16816(d[2*nh+1], ah,  bh[2], bh[3]);
                mma16816(d[2*nh],   ah,  bl[0], bl[1]);
                mma16816(d[2*nh+1], ah,  bl[2], bl[3]);
                mma16816(d[2*nh],   al4, bh[0], bh[1]);
                mma16816(d[2*nh+1], al4, bh[2], bh[3]);
            }
        }
    }
}

// Cross-group reduce: v[h][e] = sum of both K-halves for n8 block nb=g*2+h.
__device__ __forceinline__ void reduce_half(
    const float (&d)[4][4], float (&v)[2][4], float* red)
{
    const int tid = threadIdx.x;
    __syncthreads();
#pragma unroll
    for (int nb = 0; nb < 4; nb++)
#pragma unroll
        for (int e = 0; e < 4; e++)
            red[tid * 16 + nb * 4 + e] = d[nb][e];
    __syncthreads();
    const int g = tid >> 7, q = tid ^ 128;
#pragma unroll
    for (int h = 0; h < 2; h++) {
        const int nb = g * 2 + h;
#pragma unroll
        for (int e = 0; e < 4; e++)
            v[h][e] = red[tid * 16 + nb * 4 + e] + red[q * 16 + nb * 4 + e];
    }
}

extern "C" __global__ void __launch_bounds__(NTHR, 1) rnn_kernel(
    const unsigned* __restrict__ cue,
    const float* __restrict__ ec3_last,
    const float* __restrict__ ec5_last,
    const float* __restrict__ ca1bias,
    const float* __restrict__ wca3ca1,
    const float* __restrict__ wec3ca1,
    const float* __restrict__ wca1ec5,
    const float* __restrict__ wca1act,
    const float* __restrict__ actbias,
    float* __restrict__ out)
{
    extern __shared__ char sm[];
    const unsigned smb = smem_u32(sm);
    float* red = (float*)sm;

    const int tid  = threadIdx.x;
    const int b    = blockIdx.x;
    const int gh   = tid >> 7, p = tid & 127;
    const int warp_p = p >> 5, lane_p = p & 31;
    const int wm = warp_p >> 1, wn = warp_p & 1;
    const int tr = lane_p >> 2, tc = (lane_p & 3) * 2;
    const int grp = b >> 4;
    const int m0  = grp * TM;
    const int n0  = (b & 15) * TN;

    // ---- phase 0: state copy+split, ca3 split, weight split ----
    {
        const int gs = NBLK * NTHR;
        for (int i = b * NTHR + tid; i < BSZ * NN; i += gs) {
            const float e3 = ec3_last[i], e5 = ec5_last[i];
            g_ec3[i] = e3; g_ec5[i] = e5;
            const __nv_bfloat16 h = __float2bfloat16_rn(e3);
            g_ec3h[i] = h;
            g_ec3l[i] = __float2bfloat16_rn(e3 - __bfloat162float(h));
        }
        for (int i = b * NTHR + tid; i < 128 * NN; i += gs) {
            const int trow = i >> 10, k = i & 1023;
            float v = 0.0f;
            if (trow < TT) {
                const float c = (100.0f / 1023.0f) * (float)k;   // linspace(0,100,1024)
                const float dd = c - (float)trow;
                v = expf(-dd * dd * 0.02f);
            }
            const __nv_bfloat16 h = __float2bfloat16_rn(v);
            g_ca3h[i] = h;
            g_ca3l[i] = __float2bfloat16_rn(v - __bfloat162float(h));
        }
        for (int i = b * NTHR + tid; i < NN * NN; i += gs) {
            const float v0 = wca3ca1[i];
            const float v1 = wec3ca1[i];
            const float v2 = wca1ec5[i];
            const __nv_bfloat16 h0 = __float2bfloat16_rn(v0);
            const __nv_bfloat16 h1 = __float2bfloat16_rn(v1);
            const __nv_bfloat16 h2 = __float2bfloat16_rn(v2);
            g_w0h[i] = h0; g_w0l[i] = __float2bfloat16_rn(v0 - __bfloat162float(h0));
            g_w1h[i] = h1; g_w1l[i] = __float2bfloat16_rn(v1 - __bfloat162float(h1));
            g_w2h[i] = h2; g_w2l[i] = __float2bfloat16_rn(v2 - __bfloat162float(h2));
        }
    }
    FULL_SYNC();

    // ---- GEMM0: drive = ca3all @ wca3ca1 (M=100 pad 128), CTAs 0..63 ----
    if (b < 64) {
        const int m0g = (b >> 4) * TM;
        const int n0g = (b & 15) * TN;
        float d[4][4], v[2][4];
        gemm_split(g_ca3h + m0g * NN, g_ca3l + m0g * NN, g_w0h, g_w0l,
                   n0g, sm, smb, d);
        reduce_half(d, v, red);
#pragma unroll
        for (int h = 0; h < 2; h++) {
            const int nb = gh * 2 + h;
#pragma unroll
            for (int e = 0; e < 4; e++) {
                const int m = m0g + wm * 16 + tr + ((e >> 1) << 3);
                const int n = n0g + wn * 32 + nb * 8 + tc + (e & 1);
                if (m < TT) g_drive[m * NN + n] = v[h][e];
            }
        }
    }
    FULL_SYNC();

    // ---- recurrent scan: 8 independent groups of 16 CTAs ----
    for (int t = 0; t < TT; t++) {
        float d[4][4], v[2][4];

        // GEMM1: ca1 = relu(drive_t * (1+sigm(ec3@W1)) - bias)
        gemm_split(g_ec3h + m0 * NN, g_ec3l + m0 * NN, g_w1h, g_w1l,
                   n0, sm, smb, d);
        reduce_half(d, v, red);
#pragma unroll
        for (int h = 0; h < 2; h++) {
            const int nb = gh * 2 + h;
#pragma unroll
            for (int e = 0; e < 4; e++) {
                const int m = m0 + wm * 16 + tr + ((e >> 1) << 3);
                const int n = n0 + wn * 32 + nb * 8 + tc + (e & 1);
                const int idx = m * NN + n;
                float val = g_drive[t * NN + n] * (1.0f + sigm(v[h][e])) - ca1bias[n];
                val = fmaxf(val, 0.0f);
                g_ca1[idx] = val;
                const __nv_bfloat16 hh = __float2bfloat16_rn(val);
                g_ca1h[idx] = hh;
                g_ca1l[idx] = __float2bfloat16_rn(val - __bfloat162float(hh));
                if (m == 0)      out[O_C1H + t * NN + n] = val;
                if (t == TT - 1) out[O_C1F + idx] = val;
            }
        }
        GROUP_SYNC(grp);

        // GEMM2: ec5' = squash(ec5 + ca1@W2); ec3' = ec5'*ec3 (+ cue mask)
        gemm_split(g_ca1h + m0 * NN, g_ca1l + m0 * NN, g_w2h, g_w2l,
                   n0, sm, smb, d);
        reduce_half(d, v, red);
#pragma unroll
        for (int h = 0; h < 2; h++) {
            const int nb = gh * 2 + h;
#pragma unroll
            for (int e = 0; e < 4; e++) {
                const int m = m0 + wm * 16 + tr + ((e >> 1) << 3);
                const int n = n0 + wn * 32 + nb * 8 + tc + (e & 1);
                const int idx = m * NN + n;
                float e5 = g_ec5[idx] + v[h][e];
                e5 = 0.69f + 0.3f * sigm(4.0f * (e5 - 0.3f));
                float e3 = e5 * g_ec3[idx];
                // cueloc = 8*(s+2): t==16 -> cue[:,0,:], t==24 -> cue[:,1,:]
                if (t == 16 && cue[m * 2048 + n]        != 0u) e3 = 0.4f * e3 + 0.6f;
                if (t == 24 && cue[m * 2048 + 1024 + n] != 0u) e3 = 0.4f * e3 + 0.6f;
                g_ec5[idx] = e5;
                g_ec3[idx] = e3;
                const __nv_bfloat16 hh = __float2bfloat16_rn(e3);
                g_ec3h[idx] = hh;
                g_ec3l[idx] = __float2bfloat16_rn(e3 - __bfloat162float(hh));
                if (m == 0) {
                    out[O_E3H + t * NN + n] = e3;
                    out[O_E5H + t * NN + n] = e5;
                }
                if (t == TT - 1) {
                    out[O_E3F + idx] = e3;
                    out[O_E5F + idx] = e5;
                }
            }
        }
        GROUP_SYNC(grp);
    }

    // ---- actCell = ca1_final @ wca1act + actbias (rows 2b, 2b+1) ----
    {
        const int warp = tid >> 5, lane = tid & 31;
        if (warp < 4) {
            const int r = 2 * b + (warp >> 1);
            const int a = warp & 1;
            float s = 0.0f;
            for (int k = lane; k < NN; k += 32)
                s = fmaf(g_ca1[r * NN + k], wca1act[k * 2 + a], s);
#pragma unroll
            for (int off = 16; off; off >>= 1)
                s += __shfl_xor_sync(0xffffffffu, s, off);
            if (lane == 0) out[O_ACT + r * 2 + a] = s + actbias[a];
        }
    }
}

extern "C" void kernel_launch(void* const* d_in, const int* in_sizes, int n_in,
                              void* d_out, int out_size)
{
    // metadata order: cue, ec3_last, ec5_last, ca1_last, ca1bias, wca3ca1,
    //                 wec3ca1, wca1ec5, wca1act, actbias
    rnn_kernel<<<NBLK, NTHR, SMEM_TOTAL>>>(
        (const unsigned*)d_in[0],
        (const float*)d_in[1],
        (const float*)d_in[2],
        (const float*)d_in[4],
        (const float*)d_in[5],
        (const float*)d_in[6],
        (const float*)d_in[7],
        (const float*)d_in[8],
        (const float*)d_in[9],
        (float*)d_out);
}

// round 9
// speedup vs baseline: 1.1616x; 1.1616x over previous
#include <cuda_runtime.h>
#include <cuda_bf16.h>
#include <math.h>

#define BSZ  256
#define NN   1024
#define TT   100
#define NBLK 256
#define NTHR 128
#define TM   32
#define TN   32
#define KC   32
#define NCH  32
#define STAGE 8192          // A 4K (h|l per 128B row) | B 4K (h|l per 128B row)
#define NSTG  3
#define SMEM_TOTAL (NSTG * STAGE)   // 24576/CTA -> 2 CTAs/SM

// Output layout (floats)
#define O_ACT 0
#define O_E3H 512
#define O_E5H (512 + 102400)
#define O_C1H (512 + 2*102400)
#define O_E3F (512 + 3*102400)
#define O_E5F (O_E3F + 262144)
#define O_C1F (O_E5F + 262144)

// ---- persistent device state ----
__device__ float g_ec5[BSZ*NN];
__device__ float g_ec3[BSZ*NN];
__device__ float g_ca1[BSZ*NN];
__device__ float g_drive[TT*NN];
__device__ __align__(16) __nv_bfloat16 g_ec3h[BSZ*NN], g_ec3l[BSZ*NN];
__device__ __align__(16) __nv_bfloat16 g_ca1h[BSZ*NN], g_ca1l[BSZ*NN];
__device__ __align__(16) __nv_bfloat16 g_ca3h[128*NN], g_ca3l[128*NN];
__device__ __align__(16) __nv_bfloat16 g_w0h[NN*NN], g_w0l[NN*NN];  // wca3ca1 [k][n]
__device__ __align__(16) __nv_bfloat16 g_w1h[NN*NN], g_w1l[NN*NN];  // wec3ca1 [k][n]
__device__ __align__(16) __nv_bfloat16 g_w2h[NN*NN], g_w2l[NN*NN];  // wca1ec5 [k][n]
__device__ unsigned g_full = 0;
__device__ unsigned g_grp[8 * 32];

__device__ __forceinline__ float sigm(float x) {
    return __fdividef(1.0f, 1.0f + __expf(-x));
}
__device__ __forceinline__ unsigned smem_u32(const void* p) {
    unsigned a;
    asm("{ .reg .u64 t; cvta.to.shared.u64 t, %1; cvt.u32.u64 %0, t; }" : "=r"(a) : "l"(p));
    return a;
}
#define SWZ128(o) ((unsigned)(o) ^ ((((unsigned)(o)) >> 3) & 0x70u))
#define CP_ASYNC16(dst, src) \
    asm volatile("cp.async.cg.shared.global [%0], [%1], 16;" :: "r"(dst), "l"(src) : "memory")
#define CP_COMMIT()  asm volatile("cp.async.commit_group;" ::: "memory")
#define CP_WAIT1()   asm volatile("cp.async.wait_group 1;" ::: "memory")

__device__ __forceinline__ void ldm_a(unsigned (&r)[4], unsigned a) {
    asm volatile("ldmatrix.sync.aligned.m8n8.x4.shared.b16 {%0,%1,%2,%3}, [%4];"
        : "=r"(r[0]), "=r"(r[1]), "=r"(r[2]), "=r"(r[3]) : "r"(a));
}
__device__ __forceinline__ void ldm_bt(unsigned (&r)[4], unsigned a) {
    asm volatile("ldmatrix.sync.aligned.m8n8.x4.trans.shared.b16 {%0,%1,%2,%3}, [%4];"
        : "=r"(r[0]), "=r"(r[1]), "=r"(r[2]), "=r"(r[3]) : "r"(a));
}
__device__ __forceinline__ void mma16816(float (&d)[4], const unsigned (&a)[4],
                                         unsigned b0, unsigned b1) {
    asm volatile(
        "mma.sync.aligned.m16n8k16.row.col.f32.bf16.bf16.f32 "
        "{%0,%1,%2,%3}, {%4,%5,%6,%7}, {%8,%9}, {%0,%1,%2,%3};"
        : "+f"(d[0]), "+f"(d[1]), "+f"(d[2]), "+f"(d[3])
        : "r"(a[0]), "r"(a[1]), "r"(a[2]), "r"(a[3]), "r"(b0), "r"(b1));
}

// Ticket barrier (race-free, wrap-safe; N power of 2)
__device__ __forceinline__ void ticket_sync(unsigned* ctr, unsigned N) {
    __syncthreads();
    if (threadIdx.x == 0) {
        __threadfence();
        const unsigned r    = atomicAdd(ctr, 1u);
        const unsigned goal = (r & ~(N - 1u)) + N;
        while ((*(volatile unsigned*)ctr) - r < goal - r) { }
        __threadfence();
    }
    __syncthreads();
}
#define FULL_SYNC()    ticket_sync(&g_full, NBLK)
#define GROUP_SYNC(g)  ticket_sync(&g_grp[(g) << 5], 32u)

// bf16-split HMMA GEMM, 32x32 tile over K=1024, 128 threads (4 warps),
// cp.async 3-stage pipeline. Warp: wm=warp>>1 (m16), wn=warp&1 (n16).
// Accumulators separated per product (hh / hl / lh) -> 6 indep chains.
__device__ __forceinline__ void gemm32(
    const __nv_bfloat16* __restrict__ Ah, const __nv_bfloat16* __restrict__ Al,
    const __nv_bfloat16* __restrict__ Bh, const __nv_bfloat16* __restrict__ Bl,
    int n0, unsigned smb, float (&v)[2][4])
{
    const int tid  = threadIdx.x;
    const int warp = tid >> 5, lane = tid & 31;
    const int wm = warp >> 1, wn = warp & 1;
    const int sel = lane >> 3, r8 = lane & 7;

    float hh[2][4], hl[2][4], lh[2][4];
#pragma unroll
    for (int nb = 0; nb < 2; nb++)
#pragma unroll
        for (int e = 0; e < 4; e++) { hh[nb][e] = 0.f; hl[nb][e] = 0.f; lh[nb][e] = 0.f; }

    // cp.async loader: 512 16B-quads/stage, 4/thread (2 A + 2 B).
    // quad q (0..255 per region): row=q>>3, qc=q&7 (qc<4 -> hi, else lo).
    const int r0 = tid >> 3, q0 = tid & 7;                 // quads 0..127
    const int r1 = (tid + 128) >> 3, q1 = tid & 7;         // quads 128..255
    const unsigned dA0 = SWZ128(r0 * 128 + q0 * 16);
    const unsigned dA1 = SWZ128(r1 * 128 + q1 * 16);
    const unsigned dB0 = 4096 + dA0;
    const unsigned dB1 = 4096 + dA1;
    const __nv_bfloat16* sA0 = (q0 < 4 ? Ah + r0 * NN + q0 * 8
                                       : Al + r0 * NN + (q0 - 4) * 8);
    const __nv_bfloat16* sA1 = (q1 < 4 ? Ah + r1 * NN + q1 * 8
                                       : Al + r1 * NN + (q1 - 4) * 8);
    const __nv_bfloat16* sB0 = (q0 < 4 ? Bh + r0 * NN + n0 + q0 * 8
                                       : Bl + r0 * NN + n0 + (q0 - 4) * 8);
    const __nv_bfloat16* sB1 = (q1 < 4 ? Bh + r1 * NN + n0 + q1 * 8
                                       : Bl + r1 * NN + n0 + (q1 - 4) * 8);

    // ldmatrix tile-local offsets (pre-swizzle). A rows = m (h|l per 128B row),
    // B rows = k (h|l per 128B row).
    const unsigned a_off = (unsigned)((wm * 16 + ((sel & 1) << 3) + r8) * 128
                                      + ((sel >> 1) << 4));
    const unsigned b_off = (unsigned)((((sel & 1) << 3) + r8) * 128
                                      + (wn << 5) + ((sel >> 1) << 4));

    // prologue: issue chunks 0,1
#pragma unroll
    for (int c = 0; c < 2; c++) {
        const unsigned sb = smb + c * STAGE;
        const int ka = c * KC;                 // A element offset
        const long long kb = (long long)ka * NN;   // B element offset
        CP_ASYNC16(sb + dA0, sA0 + ka);
        CP_ASYNC16(sb + dA1, sA1 + ka);
        CP_ASYNC16(sb + dB0, sB0 + kb);
        CP_ASYNC16(sb + dB1, sB1 + kb);
        CP_COMMIT();
    }

    for (int c = 0; c < NCH; c++) {
        CP_WAIT1();            // chunk c landed (per-thread)
        __syncthreads();       // all threads' waits done; prev compute done

        if (c + 2 < NCH) {     // issue chunk c+2 into freed stage
            const unsigned sb = smb + ((c + 2) % NSTG) * STAGE;
            const int ka = (c + 2) * KC;
            const long long kb = (long long)ka * NN;
            CP_ASYNC16(sb + dA0, sA0 + ka);
            CP_ASYNC16(sb + dA1, sA1 + ka);
            CP_ASYNC16(sb + dB0, sB0 + kb);
            CP_ASYNC16(sb + dB1, sB1 + kb);
        }
        CP_COMMIT();           // every iter commits exactly one group

        const unsigned ab = smb + (c % NSTG) * STAGE;
#pragma unroll
        for (int ks = 0; ks < 2; ks++) {
            unsigned ah[4], al4[4], bh[4], bl[4];
            const unsigned ao = ab + SWZ128(a_off + ks * 32);
            ldm_a(ah,  ao);
            ldm_a(al4, ab + SWZ128(a_off + ks * 32 + 64));
            const unsigned bo = b_off + ks * 2048;
            ldm_bt(bh, ab + 4096 + SWZ128(bo));
            ldm_bt(bl, ab + 4096 + SWZ128(bo + 64));
            mma16816(hh[0], ah,  bh[0], bh[1]);
            mma16816(hh[1], ah,  bh[2], bh[3]);
            mma16816(hl[0], ah,  bl[0], bl[1]);
            mma16816(hl[1], ah,  bl[2], bl[3]);
            mma16816(lh[0], al4, bh[0], bh[1]);
            mma16816(lh[1], al4, bh[2], bh[3]);
        }
    }

#pragma unroll
    for (int nb = 0; nb < 2; nb++)
#pragma unroll
        for (int e = 0; e < 4; e++)
            v[nb][e] = hh[nb][e] + hl[nb][e] + lh[nb][e];
}

extern "C" __global__ void __launch_bounds__(NTHR, 2) rnn_kernel(
    const unsigned* __restrict__ cue,
    const float* __restrict__ ec3_last,
    const float* __restrict__ ec5_last,
    const float* __restrict__ ca1bias,
    const float* __restrict__ wca3ca1,
    const float* __restrict__ wec3ca1,
    const float* __restrict__ wca1ec5,
    const float* __restrict__ wca1act,
    const float* __restrict__ actbias,
    float* __restrict__ out)
{
    extern __shared__ char sm[];
    const unsigned smb = smem_u32(sm);

    const int tid  = threadIdx.x;
    const int b    = blockIdx.x;
    const int warp = tid >> 5, lane = tid & 31;
    const int wm = warp >> 1, wn = warp & 1;
    const int tr = lane >> 2, tc = (lane & 3) * 2;
    const int grp = b >> 5;                  // 8 groups of 32 CTAs
    const int m0  = grp * TM;
    const int n0  = (b & 31) * TN;

    // ---- phase 0: state copy+split, ca3 split, weight split ----
    {
        const int gs = NBLK * NTHR;
        for (int i = b * NTHR + tid; i < BSZ * NN; i += gs) {
            const float e3 = ec3_last[i], e5 = ec5_last[i];
            g_ec3[i] = e3; g_ec5[i] = e5;
            const __nv_bfloat16 h = __float2bfloat16_rn(e3);
            g_ec3h[i] = h;
            g_ec3l[i] = __float2bfloat16_rn(e3 - __bfloat162float(h));
        }
        for (int i = b * NTHR + tid; i < 128 * NN; i += gs) {
            const int trow = i >> 10, k = i & 1023;
            float v = 0.0f;
            if (trow < TT) {
                const float c = (100.0f / 1023.0f) * (float)k;   // linspace(0,100,1024)
                const float dd = c - (float)trow;
                v = expf(-dd * dd * 0.02f);
            }
            const __nv_bfloat16 h = __float2bfloat16_rn(v);
            g_ca3h[i] = h;
            g_ca3l[i] = __float2bfloat16_rn(v - __bfloat162float(h));
        }
        for (int i = b * NTHR + tid; i < NN * NN; i += gs) {
            const float v0 = wca3ca1[i];
            const float v1 = wec3ca1[i];
            const float v2 = wca1ec5[i];
            const __nv_bfloat16 h0 = __float2bfloat16_rn(v0);
            const __nv_bfloat16 h1 = __float2bfloat16_rn(v1);
            const __nv_bfloat16 h2 = __float2bfloat16_rn(v2);
            g_w0h[i] = h0; g_w0l[i] = __float2bfloat16_rn(v0 - __bfloat162float(h0));
            g_w1h[i] = h1; g_w1l[i] = __float2bfloat16_rn(v1 - __bfloat162float(h1));
            g_w2h[i] = h2; g_w2l[i] = __float2bfloat16_rn(v2 - __bfloat162float(h2));
        }
    }
    FULL_SYNC();

    // ---- GEMM0: drive = ca3all @ wca3ca1 (M=100 pad 128), CTAs 0..127 ----
    if (b < 128) {
        const int m0g = (b >> 5) * TM;
        const int n0g = (b & 31) * TN;
        float v[2][4];
        gemm32(g_ca3h + m0g * NN, g_ca3l + m0g * NN, g_w0h, g_w0l, n0g, smb, v);
#pragma unroll
        for (int nb = 0; nb < 2; nb++)
#pragma unroll
            for (int e = 0; e < 4; e++) {
                const int m = m0g + wm * 16 + tr + ((e >> 1) << 3);
                const int n = n0g + wn * 16 + nb * 8 + tc + (e & 1);
                if (m < TT) g_drive[m * NN + n] = v[nb][e];
            }
    }
    FULL_SYNC();

    // ---- recurrent scan: 8 independent groups of 32 CTAs ----
    for (int t = 0; t < TT; t++) {
        float v[2][4];

        // GEMM1: ca1 = relu(drive_t * (1+sigm(ec3@W1)) - bias)
        gemm32(g_ec3h + m0 * NN, g_ec3l + m0 * NN, g_w1h, g_w1l, n0, smb, v);
#pragma unroll
        for (int nb = 0; nb < 2; nb++)
#pragma unroll
            for (int e = 0; e < 4; e++) {
                const int m = m0 + wm * 16 + tr + ((e >> 1) << 3);
                const int n = n0 + wn * 16 + nb * 8 + tc + (e & 1);
                const int idx = m * NN + n;
                float val = g_drive[t * NN + n] * (1.0f + sigm(v[nb][e])) - ca1bias[n];
                val = fmaxf(val, 0.0f);
                g_ca1[idx] = val;
                const __nv_bfloat16 hh = __float2bfloat16_rn(val);
                g_ca1h[idx] = hh;
                g_ca1l[idx] = __float2bfloat16_rn(val - __bfloat162float(hh));
                if (m == 0)      out[O_C1H + t * NN + n] = val;
                if (t == TT - 1) out[O_C1F + idx] = val;
            }
        GROUP_SYNC(grp);

        // GEMM2: ec5' = squash(ec5 + ca1@W2); ec3' = ec5'*ec3 (+ cue mask)
        gemm32(g_ca1h + m0 * NN, g_ca1l + m0 * NN, g_w2h, g_w2l, n0, smb, v);
#pragma unroll
        for (int nb = 0; nb < 2; nb++)
#pragma unroll
            for (int e = 0; e < 4; e++) {
                const int m = m0 + wm * 16 + tr + ((e >> 1) << 3);
                const int n = n0 + wn * 16 + nb * 8 + tc + (e & 1);
                const int idx = m * NN + n;
                float e5 = g_ec5[idx] + v[nb][e];
                e5 = 0.69f + 0.3f * sigm(4.0f * (e5 - 0.3f));
                float e3 = e5 * g_ec3[idx];
                // cueloc = 8*(s+2): t==16 -> cue[:,0,:], t==24 -> cue[:,1,:]
                if (t == 16 && cue[m * 2048 + n]        != 0u) e3 = 0.4f * e3 + 0.6f;
                if (t == 24 && cue[m * 2048 + 1024 + n] != 0u) e3 = 0.4f * e3 + 0.6f;
                g_ec5[idx] = e5;
                g_ec3[idx] = e3;
                const __nv_bfloat16 hh = __float2bfloat16_rn(e3);
                g_ec3h[idx] = hh;
                g_ec3l[idx] = __float2bfloat16_rn(e3 - __bfloat162float(hh));
                if (m == 0) {
                    out[O_E3H + t * NN + n] = e3;
                    out[O_E5H + t * NN + n] = e5;
                }
                if (t == TT - 1) {
                    out[O_E3F + idx] = e3;
                    out[O_E5F + idx] = e5;
                }
            }
        GROUP_SYNC(grp);
    }

    // ---- actCell = ca1_final @ wca1act + actbias (row b) ----
    {
        if (warp < 2) {
            const int a = warp;
            float s = 0.0f;
            for (int k = lane; k < NN; k += 32)
                s = fmaf(g_ca1[b * NN + k], wca1act[k * 2 + a], s);
#pragma unroll
            for (int off = 16; off; off >>= 1)
                s += __shfl_xor_sync(0xffffffffu, s, off);
            if (lane == 0) out[O_ACT + b * 2 + a] = s + actbias[a];
        }
    }
}

extern "C" void kernel_launch(void* const* d_in, const int* in_sizes, int n_in,
                              void* d_out, int out_size)
{
    // metadata order: cue, ec3_last, ec5_last, ca1_last, ca1bias, wca3ca1,
    //                 wec3ca1, wca1ec5, wca1act, actbias
    rnn_kernel<<<NBLK, NTHR, SMEM_TOTAL>>>(
        (const unsigned*)d_in[0],
        (const float*)d_in[1],
        (const float*)d_in[2],
        (const float*)d_in[4],
        (const float*)d_in[5],
        (const float*)d_in[6],
        (const float*)d_in[7],
        (const float*)d_in[8],
        (const float*)d_in[9],
        (float*)d_out);
}